// round 13
// baseline (speedup 1.0000x reference)
#include <cuda_runtime.h>
#include <cuda_fp16.h>

#define NUM_POINTS 4
#define NUM_TABLES 10
#define TABLE_SIZE 35
#define LUT_N 65536

__device__ __half g_lut[LUT_N];

// ---------------------------------------------------------------------------
// Precompute: exact reference fp16 chain for every fp16 bit pattern.
// One entry per thread, 64K threads over 256 CTAs. Signals PDL dependents
// immediately (they gate on completion via griddepcontrol.wait anyway).
// ---------------------------------------------------------------------------
__global__ void build_lut_kernel(const void* __restrict__ cut_raw,
                                 const float* __restrict__ table,
                                 const float* __restrict__ scale)
{
    asm volatile("griddepcontrol.launch_dependents;");

    unsigned v = blockIdx.x * blockDim.x + threadIdx.x;
    if (v >= LUT_N) return;

    // dtype probe: f32 cut_points -> first word is exactly -65504.0f.
    const float probe = ((const float*)cut_raw)[0];
    const bool cut_is_f32 = (probe < -60000.0f && probe > -70000.0f);

    __half cut[NUM_TABLES + 1];
    #pragma unroll
    for (int i = 0; i <= NUM_TABLES; i++)
        cut[i] = cut_is_f32 ? __float2half(((const float*)cut_raw)[i])
                            : ((const __half*)cut_raw)[i];

    __half xh = __ushort_as_half((unsigned short)v);
    if (__hisnan(xh)) xh = __float2half(0.0f);          // reference NaN -> 0
    if (__hlt(xh, cut[0])) xh = cut[0];
    if (__hgt(xh, cut[NUM_TABLES])) xh = cut[NUM_TABLES];

    // searchsorted(side='right'), ci = clip(ss,1,10)-1
    int ci = 0;
    #pragma unroll
    for (int k = 1; k <= NUM_TABLES - 1; k++)
        if (__hge(xh, cut[k])) ci = k;

    __half dval = __hsub(xh, cut[ci]);
    __half temp = __hmul(dval, __float2half(scale[ci]));
    int idx = (int)__half2float(temp);                  // temp >= 0 -> trunc == floor
    idx = max(0, min(idx, NUM_POINTS));
    if (ci == NUM_TABLES - 1 && idx == 1) idx = 0;
    __half dec = __hsub(temp, __float2half((float)idx));
    int tbl = (ci == 0) ? idx : (1 + (ci - 1) * NUM_POINTS + idx);
    tbl = min(tbl, TABLE_SIZE - 2);
    __half lh = __float2half(table[tbl]);
    __half rh = __float2half(table[tbl + 1]);
    __half y = __hadd(lh, __hmul(__hsub(rh, lh), dec)); // two fp16 roundings
    if (__hle(xh, cut[0])) y = __float2half(table[0]);
    if (__hge(xh, cut[NUM_TABLES])) y = __float2half(table[TABLE_SIZE - 1]);

    g_lut[v] = y;
}

// ---------------------------------------------------------------------------
// Main: PDL-gated. Prologue (input constants) runs while build finishes,
// then griddepcontrol.wait orders g_lut visibility, then stage + stream.
// The streaming loop is the measured-83us version, unchanged.
// ---------------------------------------------------------------------------
__global__ __launch_bounds__(1024, 1)
void fplut_main(const float4* __restrict__ x4,
                float4* __restrict__ out4,
                int n4,
                const float* __restrict__ x,
                float* __restrict__ out,
                int n,
                const void* __restrict__ cut_raw)
{
    extern __shared__ __half s_lut[];   // 65536 entries = 128 KB

    // prologue: clip constants (independent of g_lut)
    const float probe = ((const float*)cut_raw)[0];
    const bool cut_is_f32 = (probe < -60000.0f && probe > -70000.0f);
    __half c0h, clh;
    if (cut_is_f32) {
        c0h = __float2half(((const float*)cut_raw)[0]);
        clh = __float2half(((const float*)cut_raw)[NUM_TABLES]);
    } else {
        c0h = ((const __half*)cut_raw)[0];
        clh = ((const __half*)cut_raw)[NUM_TABLES];
    }
    const __half2 c0_2 = __half2half2(c0h);
    const __half2 cl_2 = __half2half2(clh);

    // wait for build kernel's g_lut writes to be visible
    asm volatile("griddepcontrol.wait;" ::: "memory");

    // stage LUT: 128 KB / 1024 threads = 8 x uint4 per thread (independent)
    {
        const uint4* src = (const uint4*)g_lut;
        uint4*       dst = (uint4*)s_lut;
        #pragma unroll
        for (int i = threadIdx.x; i < LUT_N * 2 / 16; i += 1024)
            dst[i] = src[i];
    }
    __syncthreads();

    const int stride = gridDim.x * blockDim.x;
    int i = blockIdx.x * blockDim.x + threadIdx.x;

    // main loop: 8 independent streaming loads in flight per warp
    for (; i + 7 * stride < n4; i += 8 * stride) {
        float4 vv[8];
        #pragma unroll
        for (int b = 0; b < 8; b++)
            vv[b] = __ldcs(&x4[i + b * stride]);

        #pragma unroll
        for (int b = 0; b < 8; b++) {
            // pack + clip in fp16 SIMD. NaN -> c0 index (LUT[c0]=table[0]=y(0)
            // matches reference NaN->0). f32 overflow -> inf -> clipped here.
            __half2 h01 = __hmin2(__hmax2(__floats2half2_rn(vv[b].x, vv[b].y), c0_2), cl_2);
            __half2 h23 = __hmin2(__hmax2(__floats2half2_rn(vv[b].z, vv[b].w), c0_2), cl_2);
            unsigned b01 = *reinterpret_cast<const unsigned*>(&h01);
            unsigned b23 = *reinterpret_cast<const unsigned*>(&h23);
            float4 r = make_float4(__half2float(s_lut[b01 & 0xFFFFu]),
                                   __half2float(s_lut[b01 >> 16]),
                                   __half2float(s_lut[b23 & 0xFFFFu]),
                                   __half2float(s_lut[b23 >> 16]));
            __stcs(&out4[i + b * stride], r);
        }
    }

    // remainder (0..7 iterations per thread)
    for (; i < n4; i += stride) {
        float4 v = __ldcs(&x4[i]);
        __half2 h01 = __hmin2(__hmax2(__floats2half2_rn(v.x, v.y), c0_2), cl_2);
        __half2 h23 = __hmin2(__hmax2(__floats2half2_rn(v.z, v.w), c0_2), cl_2);
        unsigned b01 = *reinterpret_cast<const unsigned*>(&h01);
        unsigned b23 = *reinterpret_cast<const unsigned*>(&h23);
        float4 r = make_float4(__half2float(s_lut[b01 & 0xFFFFu]),
                               __half2float(s_lut[b01 >> 16]),
                               __half2float(s_lut[b23 & 0xFFFFu]),
                               __half2float(s_lut[b23 >> 16]));
        __stcs(&out4[i], r);
    }

    // scalar tail (n not multiple of 4); no-op for this problem's shapes
    for (int j = n4 * 4 + blockIdx.x * blockDim.x + threadIdx.x; j < n;
         j += stride) {
        __half xh = __float2half(fminf(fmaxf(x[j], __half2float(c0h)),
                                       __half2float(clh)));
        out[j] = __half2float(s_lut[(unsigned)__half_as_ushort(xh)]);
    }
}

extern "C" void kernel_launch(void* const* d_in, const int* in_sizes, int n_in,
                              void* d_out, int out_size)
{
    const float* x     = (const float*)d_in[0];
    const void*  cut   = d_in[1];
    const float* table = (const float*)d_in[2];
    const float* scale = (const float*)d_in[3];
    float* out = (float*)d_out;

    int n  = in_sizes[0];
    int n4 = n / 4;

    int sms = 148;
    cudaDeviceGetAttribute(&sms, cudaDevAttrMultiProcessorCount, 0);

    cudaFuncSetAttribute(fplut_main,
                         cudaFuncAttributeMaxDynamicSharedMemorySize,
                         LUT_N * (int)sizeof(__half));

    build_lut_kernel<<<256, 256>>>(cut, table, scale);

    // PDL launch of the main kernel: overlap its dispatch with build_lut.
    cudaLaunchConfig_t cfg = {};
    cfg.gridDim = dim3(sms, 1, 1);
    cfg.blockDim = dim3(1024, 1, 1);
    cfg.dynamicSmemBytes = LUT_N * sizeof(__half);
    cudaLaunchAttribute attr[1];
    attr[0].id = cudaLaunchAttributeProgrammaticStreamSerialization;
    attr[0].val.programmaticStreamSerializationAllowed = 1;
    cfg.attrs = attr;
    cfg.numAttrs = 1;

    cudaError_t e = cudaLaunchKernelEx(&cfg, fplut_main,
                                       (const float4*)x, (float4*)out, n4,
                                       x, out, n, (const void*)cut);
    if (e != cudaSuccess) {
        // fallback: plain serialized launch (griddepcontrol.wait is a no-op
        // when no PDL dependency exists)
        fplut_main<<<sms, 1024, LUT_N * (int)sizeof(__half)>>>(
            (const float4*)x, (float4*)out, n4, x, out, n, cut);
    }
}

// round 14
// speedup vs baseline: 1.0648x; 1.0648x over previous
#include <cuda_runtime.h>
#include <cuda_fp16.h>

#define NUM_POINTS 4
#define NUM_TABLES 10
#define TABLE_SIZE 35
#define LUT_N 65536
#define CHUNK 8192          // float4 elements per work-steal chunk (512 KB)

__device__ __half g_lut[LUT_N];
__device__ unsigned g_chunk_ctr;

// ---------------------------------------------------------------------------
// Precompute: exact reference fp16 chain for every fp16 bit pattern.
// One entry per thread, 64K threads over 256 CTAs. Also resets the work-steal
// counter (this kernel is graph-ordered before fplut_main every replay).
// ---------------------------------------------------------------------------
__global__ void build_lut_kernel(const void* __restrict__ cut_raw,
                                 const float* __restrict__ table,
                                 const float* __restrict__ scale)
{
    if (blockIdx.x == 0 && threadIdx.x == 0) g_chunk_ctr = 0;

    unsigned v = blockIdx.x * blockDim.x + threadIdx.x;
    if (v >= LUT_N) return;

    // dtype probe: f32 cut_points -> first word is exactly -65504.0f.
    const float probe = ((const float*)cut_raw)[0];
    const bool cut_is_f32 = (probe < -60000.0f && probe > -70000.0f);

    __half cut[NUM_TABLES + 1];
    #pragma unroll
    for (int i = 0; i <= NUM_TABLES; i++)
        cut[i] = cut_is_f32 ? __float2half(((const float*)cut_raw)[i])
                            : ((const __half*)cut_raw)[i];

    __half xh = __ushort_as_half((unsigned short)v);
    if (__hisnan(xh)) xh = __float2half(0.0f);          // reference NaN -> 0
    if (__hlt(xh, cut[0])) xh = cut[0];
    if (__hgt(xh, cut[NUM_TABLES])) xh = cut[NUM_TABLES];

    // searchsorted(side='right'), ci = clip(ss,1,10)-1
    int ci = 0;
    #pragma unroll
    for (int k = 1; k <= NUM_TABLES - 1; k++)
        if (__hge(xh, cut[k])) ci = k;

    __half dval = __hsub(xh, cut[ci]);
    __half temp = __hmul(dval, __float2half(scale[ci]));
    int idx = (int)__half2float(temp);                  // temp >= 0 -> trunc == floor
    idx = max(0, min(idx, NUM_POINTS));
    if (ci == NUM_TABLES - 1 && idx == 1) idx = 0;
    __half dec = __hsub(temp, __float2half((float)idx));
    int tbl = (ci == 0) ? idx : (1 + (ci - 1) * NUM_POINTS + idx);
    tbl = min(tbl, TABLE_SIZE - 2);
    __half lh = __float2half(table[tbl]);
    __half rh = __float2half(table[tbl + 1]);
    __half y = __hadd(lh, __hmul(__hsub(rh, lh), dec)); // two fp16 roundings
    if (__hle(xh, cut[0])) y = __float2half(table[0]);
    if (__hge(xh, cut[NUM_TABLES])) y = __float2half(table[TABLE_SIZE - 1]);

    g_lut[v] = y;
}

// ---------------------------------------------------------------------------
// Main: persistent CTAs steal contiguous 8192-float4 chunks via an atomic
// counter, eliminating the static-partition straggler tail (between-SM
// L2-die spread ~1.1x). Inner body = the measured batch-of-8 streaming loop.
// ---------------------------------------------------------------------------
__global__ __launch_bounds__(1024, 1)
void fplut_main(const float4* __restrict__ x4,
                float4* __restrict__ out4,
                int n4,
                const float* __restrict__ x,
                float* __restrict__ out,
                int n,
                const void* __restrict__ cut_raw)
{
    extern __shared__ __half s_lut[];   // 65536 entries = 128 KB
    __shared__ unsigned s_chunk;

    // stage LUT: 128 KB / 1024 threads = 8 x uint4 per thread (independent)
    {
        const uint4* src = (const uint4*)g_lut;
        uint4*       dst = (uint4*)s_lut;
        #pragma unroll
        for (int i = threadIdx.x; i < LUT_N * 2 / 16; i += 1024)
            dst[i] = src[i];
    }

    const float probe = ((const float*)cut_raw)[0];
    const bool cut_is_f32 = (probe < -60000.0f && probe > -70000.0f);
    __half c0h, clh;
    if (cut_is_f32) {
        c0h = __float2half(((const float*)cut_raw)[0]);
        clh = __float2half(((const float*)cut_raw)[NUM_TABLES]);
    } else {
        c0h = ((const __half*)cut_raw)[0];
        clh = ((const __half*)cut_raw)[NUM_TABLES];
    }
    const __half2 c0_2 = __half2half2(c0h);
    const __half2 cl_2 = __half2half2(clh);

    const int tid = threadIdx.x;
    const unsigned nchunks = (unsigned)((n4 + CHUNK - 1) / CHUNK);

    for (;;) {
        __syncthreads();                    // also covers initial LUT staging
        if (tid == 0) s_chunk = atomicAdd(&g_chunk_ctr, 1u);
        __syncthreads();
        const unsigned c = s_chunk;
        if (c >= nchunks) break;

        const int base = (int)c * CHUNK + tid;

        if ((int)c * CHUNK + CHUNK <= n4) {
            // full chunk: 8 independent streaming loads in flight per warp
            float4 vv[8];
            #pragma unroll
            for (int b = 0; b < 8; b++)
                vv[b] = __ldcs(&x4[base + b * 1024]);

            #pragma unroll
            for (int b = 0; b < 8; b++) {
                // pack + clip in fp16 SIMD. NaN -> c0 index (LUT[c0]=table[0]
                // = y(0), matching reference NaN->0). f32 overflow -> inf ->
                // clipped here.
                __half2 h01 = __hmin2(__hmax2(__floats2half2_rn(vv[b].x, vv[b].y), c0_2), cl_2);
                __half2 h23 = __hmin2(__hmax2(__floats2half2_rn(vv[b].z, vv[b].w), c0_2), cl_2);
                unsigned b01 = *reinterpret_cast<const unsigned*>(&h01);
                unsigned b23 = *reinterpret_cast<const unsigned*>(&h23);
                float4 r = make_float4(__half2float(s_lut[b01 & 0xFFFFu]),
                                       __half2float(s_lut[b01 >> 16]),
                                       __half2float(s_lut[b23 & 0xFFFFu]),
                                       __half2float(s_lut[b23 >> 16]));
                __stcs(&out4[base + b * 1024], r);
            }
        } else {
            // partial last chunk (not hit for this problem's 2048*8192 split)
            #pragma unroll
            for (int b = 0; b < 8; b++) {
                int i = base + b * 1024;
                if (i < n4) {
                    float4 v = __ldcs(&x4[i]);
                    __half2 h01 = __hmin2(__hmax2(__floats2half2_rn(v.x, v.y), c0_2), cl_2);
                    __half2 h23 = __hmin2(__hmax2(__floats2half2_rn(v.z, v.w), c0_2), cl_2);
                    unsigned b01 = *reinterpret_cast<const unsigned*>(&h01);
                    unsigned b23 = *reinterpret_cast<const unsigned*>(&h23);
                    float4 r = make_float4(__half2float(s_lut[b01 & 0xFFFFu]),
                                           __half2float(s_lut[b01 >> 16]),
                                           __half2float(s_lut[b23 & 0xFFFFu]),
                                           __half2float(s_lut[b23 >> 16]));
                    __stcs(&out4[i], r);
                }
            }
        }
    }

    // scalar tail (n not multiple of 4); no-op for this problem's shapes
    const int gstride = gridDim.x * blockDim.x;
    for (int j = n4 * 4 + blockIdx.x * blockDim.x + tid; j < n; j += gstride) {
        __half xh = __float2half(fminf(fmaxf(x[j], __half2float(c0h)),
                                       __half2float(clh)));
        out[j] = __half2float(s_lut[(unsigned)__half_as_ushort(xh)]);
    }
}

extern "C" void kernel_launch(void* const* d_in, const int* in_sizes, int n_in,
                              void* d_out, int out_size)
{
    const float* x     = (const float*)d_in[0];
    const void*  cut   = d_in[1];
    const float* table = (const float*)d_in[2];
    const float* scale = (const float*)d_in[3];
    float* out = (float*)d_out;

    int n  = in_sizes[0];
    int n4 = n / 4;

    int sms = 148;
    cudaDeviceGetAttribute(&sms, cudaDevAttrMultiProcessorCount, 0);

    cudaFuncSetAttribute(fplut_main,
                         cudaFuncAttributeMaxDynamicSharedMemorySize,
                         LUT_N * (int)sizeof(__half));

    // 64K threads, one LUT entry each + work-steal counter reset
    build_lut_kernel<<<256, 256>>>(cut, table, scale);
    fplut_main<<<sms, 1024, LUT_N * (int)sizeof(__half)>>>(
        (const float4*)x, (float4*)out, n4, x, out, n, cut);
}